// round 2
// baseline (speedup 1.0000x reference)
#include <cuda_runtime.h>
#include <cstddef>

#define NPTS 1000000
#define KSZ 9
#define CCH 16
#define EPSBN 1e-5f
#define NF4 (NPTS * CCH / 4)
#define CONVGRID 15625            // 64 points per block * 15625 = 1M
#define MIDB 64
#define RPB 245                   // ceil(15625/64)
#define SGRID 1184
#define SSTRIDE (SGRID * 256)

// ---------------- scratch (device globals: no allocation) ----------------
__device__ float g_h[(size_t)NPTS * CCH];          // conv1 raw output, 64 MB
__device__ float4 g_part4[CONVGRID * 8];           // per-conv-block stats partials
__device__ float g_mid[MIDB * 32];                 // mid-stage stats partials
__device__ __align__(16) float g_st1[32];          // BN1 scale[16], shift[16]
__device__ __align__(16) float g_st2[32];          // BN2 scale[16], shift[16]

// =====================================================================
// Fused tree-conv: 4 lanes per point (lane g owns input channels 4g..4g+3).
// Gathers are warp-coalesced (8 rows x 64B per LDG.128 wave). Reduce-scatter
// over the 4-lane group leaves lane g with outputs o = 4g..4g+3.
// Also emits per-block BN stats partials (sum, sumsq per channel).
// =====================================================================
template <bool BN, bool BIAS>
__global__ __launch_bounds__(256) void conv_kernel(
    const float* __restrict__ src, const int* __restrict__ ind,
    const float* __restrict__ w, const float* __restrict__ bias,
    float* __restrict__ dst)
{
    // smem: weights ws[2880] floats (11.5KB), later reused for stats reduce (16KB)
    __shared__ __align__(16) float sbuf[4096];
    const int tid = threadIdx.x;
    const int g = tid & 3;

    // stage weights: w[c][o][j] (c*144 + o*9 + j) -> ws[j*320 + cc*80 + g*20 + o]
    // where c = 4*g + cc.  20-float g-stride => the 4 per-warp LDS addresses hit
    // disjoint bank groups (bank offsets 0,20,8,28).
    for (int i = tid; i < CCH * CCH * KSZ; i += 256) {
        int c = i / (CCH * KSZ);
        int rem = i - c * (CCH * KSZ);
        int o = rem / KSZ;
        int j = rem - o * KSZ;
        sbuf[j * 320 + (c & 3) * 80 + (c >> 2) * 20 + o] = w[i];
    }
    __syncthreads();

    const int n = blockIdx.x * 64 + (tid >> 2);

    // BN1 affine for this lane's 4 input channels (conv2 only)
    float4 bsc, bsh;
    if (BN) {
        bsc = reinterpret_cast<const float4*>(g_st1)[g];
        bsh = reinterpret_cast<const float4*>(g_st1 + 16)[g];
    }

    float acc[16];
#pragma unroll
    for (int o = 0; o < 16; o++) acc[o] = 0.0f;

    int rows[KSZ];
    const int* ip = ind + (size_t)n * KSZ;
#pragma unroll
    for (int j = 0; j < KSZ; j++) rows[j] = ip[j];

    const float4* sp = reinterpret_cast<const float4*>(src);
#pragma unroll
    for (int j = 0; j < KSZ; j++) {
        float4 vv = __ldg(sp + (size_t)rows[j] * 4 + g);
        float vr[4] = {vv.x, vv.y, vv.z, vv.w};
        const float* wj = sbuf + j * 320 + g * 20;
#pragma unroll
        for (int cc = 0; cc < 4; cc++) {
            float vc = vr[cc];
            if (BN) {
                const float s = (cc == 0 ? bsc.x : cc == 1 ? bsc.y : cc == 2 ? bsc.z : bsc.w);
                const float h = (cc == 0 ? bsh.x : cc == 1 ? bsh.y : cc == 2 ? bsh.z : bsh.w);
                vc = fmaf(vc, s, h);
                vc = fmaxf(vc, 0.2f * vc);
            }
            const float4* wv = reinterpret_cast<const float4*>(wj + cc * 80);
#pragma unroll
            for (int o4 = 0; o4 < 4; o4++) {
                float4 ww = wv[o4];
                acc[o4 * 4 + 0] = fmaf(vc, ww.x, acc[o4 * 4 + 0]);
                acc[o4 * 4 + 1] = fmaf(vc, ww.y, acc[o4 * 4 + 1]);
                acc[o4 * 4 + 2] = fmaf(vc, ww.z, acc[o4 * 4 + 2]);
                acc[o4 * 4 + 3] = fmaf(vc, ww.w, acc[o4 * 4 + 3]);
            }
        }
    }

    // reduce-scatter over the 4-lane group.
    // stage A (xor 2): g in {0,1} keep o0..7 ; g in {2,3} keep o8..15
    float h8[8];
#pragma unroll
    for (int i = 0; i < 8; i++) {
        float a = acc[i], b = acc[i + 8];
        float mine = (g & 2) ? a : b;
        float oth = __shfl_xor_sync(0xffffffffu, mine, 2);
        h8[i] = ((g & 2) ? b : a) + oth;
    }
    // stage B (xor 1): even g keeps first 4 of its half, odd keeps last 4
    float q[4];
#pragma unroll
    for (int i = 0; i < 4; i++) {
        float a = h8[i], b = h8[i + 4];
        float mine = (g & 1) ? a : b;
        float oth = __shfl_xor_sync(0xffffffffu, mine, 1);
        q[i] = ((g & 1) ? b : a) + oth;
    }
    // lane g now holds final raw outputs for o = 4g .. 4g+3
    if (BIAS) {
        float4 b4 = reinterpret_cast<const float4*>(bias)[g];
        q[0] += b4.x; q[1] += b4.y; q[2] += b4.z; q[3] += b4.w;
    }
    float4 outv = make_float4(q[0], q[1], q[2], q[3]);
    reinterpret_cast<float4*>(dst)[(size_t)n * 4 + g] = outv;

    // ---- fused per-block BN stats (deterministic) ----
    __syncthreads();           // done with ws; reuse sbuf
    float4* s1 = reinterpret_cast<float4*>(sbuf);
    float4* s2 = s1 + 256;
    s1[tid] = outv;
    s2[tid] = make_float4(outv.x * outv.x, outv.y * outv.y,
                          outv.z * outv.z, outv.w * outv.w);
    __syncthreads();
#pragma unroll
    for (int off = 128; off >= 4; off >>= 1) {
        if (tid < off) {
            float4 a = s1[tid], b = s1[tid + off];
            a.x += b.x; a.y += b.y; a.z += b.z; a.w += b.w; s1[tid] = a;
            float4 c = s2[tid], d = s2[tid + off];
            c.x += d.x; c.y += d.y; c.z += d.z; c.w += d.w; s2[tid] = c;
        }
        __syncthreads();
    }
    if (tid < 4) {
        g_part4[blockIdx.x * 8 + tid] = s1[tid];       // sums, channels 4*tid..
        g_part4[blockIdx.x * 8 + 4 + tid] = s2[tid];   // squares
    }
}

// ---------------- mid-stage stats reduction: 15625 -> 64 partials ----------------
__global__ __launch_bounds__(256) void midstats_kernel()
{
    const float* part = reinterpret_cast<const float*>(g_part4);
    const int tid = threadIdx.x;
    const int v = tid & 31;
    const int lane = tid >> 5;
    const int r0 = blockIdx.x * RPB;
    const int rend = min(r0 + RPB, CONVGRID);
    float loc = 0.f;
    for (int r = r0 + lane; r < rend; r += 8) loc += part[r * 32 + v];
    __shared__ float sm[256];
    sm[tid] = loc;
    __syncthreads();
    if (tid < 32) {
        float t = 0.f;
#pragma unroll
        for (int k = 0; k < 8; k++) t += sm[tid + k * 32];
        g_mid[blockIdx.x * 32 + tid] = t;
    }
}

// ---------------- finalize: 64 partials -> BN scale/shift ----------------
template <int S>
__global__ void finalize_kernel(const float* __restrict__ gamma,
                                const float* __restrict__ beta)
{
    const int tid = threadIdx.x;   // 32 threads
    __shared__ float sm[32];
    float t = 0.f;
    for (int r = 0; r < MIDB; r++) t += g_mid[r * 32 + tid];
    sm[tid] = t;
    __syncthreads();
    if (tid < 16) {
        const float inv_n = 1.0f / (float)NPTS;
        float mean = sm[tid] * inv_n;
        float var = sm[16 + tid] * inv_n - mean * mean;
        float rstd = rsqrtf(var + EPSBN);
        float sc = gamma[tid] * rstd;
        float sh = beta[tid] - mean * sc;
        float* st = (S == 1) ? g_st1 : g_st2;
        st[tid] = sc;
        st[16 + tid] = sh;
    }
}

// ---------- epilogue: out = leaky(BN2(raw2) + data), in place on d_out ----------
__global__ __launch_bounds__(256) void bnres_kernel(
    const float* __restrict__ data, float* __restrict__ out)
{
    const int tid = threadIdx.x;
    const int idx = blockIdx.x * 256 + tid;
    const int g = tid & 3;
    float4 sc = reinterpret_cast<const float4*>(g_st2)[g];
    float4 sh = reinterpret_cast<const float4*>(g_st2 + 16)[g];
    const float4* dd = reinterpret_cast<const float4*>(data);
    float4* oo = reinterpret_cast<float4*>(out);
    for (int i = idx; i < NF4; i += SSTRIDE) {
        float4 r = oo[i];
        float4 d = dd[i];
        float4 y;
        y.x = fmaf(r.x, sc.x, sh.x) + d.x;
        y.y = fmaf(r.y, sc.y, sh.y) + d.y;
        y.z = fmaf(r.z, sc.z, sh.z) + d.z;
        y.w = fmaf(r.w, sc.w, sh.w) + d.w;
        y.x = fmaxf(y.x, 0.2f * y.x);
        y.y = fmaxf(y.y, 0.2f * y.y);
        y.z = fmaxf(y.z, 0.2f * y.z);
        y.w = fmaxf(y.w, 0.2f * y.w);
        oo[i] = y;
    }
}

extern "C" void kernel_launch(void* const* d_in, const int* in_sizes, int n_in,
                              void* d_out, int out_size)
{
    const float* data   = (const float*)d_in[0];
    const int*   ind    = (const int*)  d_in[1];
    const float* w1     = (const float*)d_in[2];
    const float* b1     = (const float*)d_in[3];
    const float* gamma1 = (const float*)d_in[4];
    const float* beta1  = (const float*)d_in[5];
    const float* w2     = (const float*)d_in[6];
    const float* gamma2 = (const float*)d_in[7];
    const float* beta2  = (const float*)d_in[8];
    float* out = (float*)d_out;

    float* gh;
    cudaGetSymbolAddress((void**)&gh, g_h);

    conv_kernel<false, true><<<CONVGRID, 256>>>(data, ind, w1, b1, gh);
    midstats_kernel<<<MIDB, 256>>>();
    finalize_kernel<1><<<1, 32>>>(gamma1, beta1);
    conv_kernel<true, false><<<CONVGRID, 256>>>(gh, ind, w2, nullptr, out);
    midstats_kernel<<<MIDB, 256>>>();
    finalize_kernel<2><<<1, 32>>>(gamma2, beta2);
    bnres_kernel<<<SGRID, 256>>>(data, out);
}